// round 11
// baseline (speedup 1.0000x reference)
#include <cuda_runtime.h>
#include <cuda_bf16.h>

// NuclearLossFunc: loss = sum(x^2) / (B*C), x: (32,64,256,256) fp32
// = 134,217,728 elements = 512 MiB read. HBM-bound reduction.
//
// R11: R6 skeleton (best: 80.58us kernel) with BLOCKED address mapping:
// each CTA owns a contiguous ~900KB region and streams it sequentially
// in 8KB steps (512 thr x float4). 592 long sequential DRAM streams
// instead of grid-stride's shuffled interleave -> max row-buffer hits.
// Loop instruction shape identical to R6 (constant-stride load + fmas).
// 65536 x 8KB chunks split 416 CTAs x 111 + 176 x 110.
// Deterministic: fixed trees, final accumulate in double.

#define NBLOCKS  592            // 148 SMs * 4 CTAs -> one wave
#define NTHREADS 512
#define NCHUNKS  65536          // 8KB chunks (512 float4)
#define BASECNT  110            // NCHUNKS = 592*110 + 416
#define EXTRA    416

__device__ double       g_partials[NBLOCKS];
__device__ unsigned int g_count;   // zero-initialized at module load

__global__ __launch_bounds__(NTHREADS) void sqsum_blocked_kernel(
    const float4* __restrict__ in,
    float* __restrict__ out, float scale)
{
    const int lane = threadIdx.x & 31;
    const int wid  = threadIdx.x >> 5;
    __shared__ double wd[NTHREADS / 32];
    __shared__ bool   s_is_last;

    // contiguous chunk range for this CTA
    const int bid   = blockIdx.x;
    const int extra = (bid < EXTRA) ? bid : EXTRA;
    const int start = bid * BASECNT + extra;
    const int count = BASECNT + (bid < EXTRA ? 1 : 0);

    // ---- hot loop: sequential 8KB steps through the CTA's block ----
    float s0 = 0.f, s1 = 0.f, s2 = 0.f, s3 = 0.f;
    const float4* p   = in + (long long)start * NTHREADS + threadIdx.x;
    const float4* end = p + (long long)count * NTHREADS;

    for (; p < end; p += NTHREADS) {
        float4 v = *p;
        s0 = fmaf(v.x, v.x, s0);
        s1 = fmaf(v.y, v.y, s1);
        s2 = fmaf(v.z, v.z, s2);
        s3 = fmaf(v.w, v.w, s3);
    }
    double acc = (double)((s0 + s1) + (s2 + s3));

    // ---- block reduce (double, fixed tree) ----
    #pragma unroll
    for (int o = 16; o > 0; o >>= 1)
        acc += __shfl_xor_sync(0xffffffffu, acc, o);

    if (lane == 0) wd[wid] = acc;
    __syncthreads();

    if (wid == 0) {
        acc = (lane < NTHREADS / 32) ? wd[lane] : 0.0;
        #pragma unroll
        for (int o = 16; o > 0; o >>= 1)
            acc += __shfl_xor_sync(0xffffffffu, acc, o);
        if (lane == 0) g_partials[blockIdx.x] = acc;   // released by acq_rel
    }

    // ---- last-block election: one acq_rel atomic ----
    if (threadIdx.x == 0) {
        unsigned int ticket;
        asm volatile("atom.add.acq_rel.gpu.u32 %0, [%1], 1;"
                     : "=r"(ticket) : "l"(&g_count) : "memory");
        s_is_last = (ticket == (unsigned int)(gridDim.x - 1));
    }
    __syncthreads();
    if (!s_is_last) return;

    // ---- last block: reduce 592 doubles (deterministic fixed tree) ----
    double dsum = 0.0;
    for (int q = threadIdx.x; q < NBLOCKS; q += NTHREADS)
        dsum += g_partials[q];

    #pragma unroll
    for (int o = 16; o > 0; o >>= 1)
        dsum += __shfl_xor_sync(0xffffffffu, dsum, o);

    if (lane == 0) wd[wid] = dsum;
    __syncthreads();

    if (wid == 0) {
        dsum = (lane < NTHREADS / 32) ? wd[lane] : 0.0;
        #pragma unroll
        for (int o = 16; o > 0; o >>= 1)
            dsum += __shfl_xor_sync(0xffffffffu, dsum, o);
        if (lane == 0) {
            out[0] = (float)(dsum * (double)scale);
            g_count = 0;  // reset for graph replay
        }
    }
}

extern "C" void kernel_launch(void* const* d_in, const int* in_sizes, int n_in,
                              void* d_out, int out_size)
{
    const float* x = (const float*)d_in[0];
    long long n = (long long)in_sizes[0];     // 134,217,728
    // 65536 chunks * 512 float4 = n/4 exactly

    // B*C = n / (256*256) = 2048
    float scale = 1.0f / (float)(n / (256LL * 256LL));

    sqsum_blocked_kernel<<<NBLOCKS, NTHREADS>>>((const float4*)x,
                                                (float*)d_out, scale);
}

// round 12
// speedup vs baseline: 1.0813x; 1.0813x over previous
#include <cuda_runtime.h>
#include <cuda_bf16.h>
#include <cstdint>

// NuclearLossFunc: loss = sum(x^2) / (B*C), x: (32,64,256,256) fp32
// = 134,217,728 elements = 512 MiB read. HBM-bound reduction.
//
// R12: TMA bulk-copy pipeline. All LDG variants cluster at 80.6-85us
// (DRAM-active invariant ~68.2us, ~15% distributed idle). cp.async.bulk
// issues 16KB per instruction through the TMA engine — request stream
// decoupled from warp scheduling. 2-stage x 16KB smem double buffer per
// CTA (48KB static, 4 CTAs/SM), mbarrier expect_tx completion, compute
// from smem (conflict-free LDS.128). Deterministic: fixed chunk order
// per CTA, fixed trees, final accumulate in double.

#define NBLOCKS      592          // 148 SMs * 4 CTAs -> one wave
#define NTHREADS     512
#define CHUNK_BYTES  16384        // 16KB per bulk copy
#define CHUNK_F4     1024
#define TOTAL_CHUNKS 32768        // 512MiB / 16KB

__device__ double       g_partials[NBLOCKS];
__device__ unsigned int g_count;   // zero-initialized at module load

__device__ __forceinline__ uint32_t smem_u32(const void* p) {
    return (uint32_t)__cvta_generic_to_shared(p);
}

__global__ __launch_bounds__(NTHREADS) void sqsum_tma_kernel(
    const char* __restrict__ gin,
    float* __restrict__ out, float scale)
{
    __shared__ __align__(128) char buf[2][CHUNK_BYTES];
    __shared__ __align__(8) unsigned long long mbar[2];
    __shared__ double wd[NTHREADS / 32];
    __shared__ bool   s_is_last;

    const int tid  = threadIdx.x;
    const int lane = tid & 31;
    const int wid  = tid >> 5;
    const uint32_t mb0 = smem_u32(&mbar[0]);
    const uint32_t mb1 = smem_u32(&mbar[1]);
    const uint32_t sb0 = smem_u32(&buf[0][0]);
    const uint32_t sb1 = smem_u32(&buf[1][0]);

    if (tid == 0) {
        asm volatile("mbarrier.init.shared.b64 [%0], 1;" :: "r"(mb0) : "memory");
        asm volatile("mbarrier.init.shared.b64 [%0], 1;" :: "r"(mb1) : "memory");
        asm volatile("fence.proxy.async.shared::cta;" ::: "memory");
    }
    __syncthreads();

    // ---- prologue: fill both stages ----
    if (tid == 0) {
        long long c0 = blockIdx.x;
        long long c1 = blockIdx.x + NBLOCKS;
        asm volatile("mbarrier.arrive.expect_tx.shared.b64 _, [%0], %1;"
                     :: "r"(mb0), "r"((uint32_t)CHUNK_BYTES) : "memory");
        asm volatile("cp.async.bulk.shared::cta.global.mbarrier::complete_tx::bytes "
                     "[%0], [%1], %2, [%3];"
                     :: "r"(sb0), "l"(gin + c0 * CHUNK_BYTES),
                        "r"((uint32_t)CHUNK_BYTES), "r"(mb0) : "memory");
        asm volatile("mbarrier.arrive.expect_tx.shared.b64 _, [%0], %1;"
                     :: "r"(mb1), "r"((uint32_t)CHUNK_BYTES) : "memory");
        asm volatile("cp.async.bulk.shared::cta.global.mbarrier::complete_tx::bytes "
                     "[%0], [%1], %2, [%3];"
                     :: "r"(sb1), "l"(gin + c1 * CHUNK_BYTES),
                        "r"((uint32_t)CHUNK_BYTES), "r"(mb1) : "memory");
    }

    // ---- main pipeline ----
    float s0 = 0.f, s1 = 0.f, s2 = 0.f, s3 = 0.f;
    int j = 0;
    for (long long c = blockIdx.x; c < TOTAL_CHUNKS; c += NBLOCKS, ++j) {
        const int      b   = j & 1;
        const uint32_t mb  = b ? mb1 : mb0;
        const uint32_t sb  = b ? sb1 : sb0;
        const uint32_t ph  = (j >> 1) & 1;

        // wait for stage full (acquire orders subsequent smem reads)
        asm volatile(
            "{\n\t"
            ".reg .pred P;\n\t"
            "WAIT_%=:\n\t"
            "mbarrier.try_wait.parity.acquire.cta.shared::cta.b64 P, [%0], %1, 0x989680;\n\t"
            "@P bra.uni DONE_%=;\n\t"
            "bra.uni WAIT_%=;\n\t"
            "DONE_%=:\n\t"
            "}"
            :: "r"(mb), "r"(ph) : "memory");

        const float4* sp = (const float4*)(buf[b]);
        float4 u = sp[tid];
        float4 v = sp[tid + NTHREADS];
        s0 = fmaf(u.x, u.x, s0);  s1 = fmaf(u.y, u.y, s1);
        s2 = fmaf(u.z, u.z, s2);  s3 = fmaf(u.w, u.w, s3);
        s0 = fmaf(v.x, v.x, s0);  s1 = fmaf(v.y, v.y, s1);
        s2 = fmaf(v.z, v.z, s2);  s3 = fmaf(v.w, v.w, s3);

        __syncthreads();   // all threads done reading buf[b]

        long long cn = c + 2 * NBLOCKS;
        if (tid == 0 && cn < TOTAL_CHUNKS) {
            asm volatile("mbarrier.arrive.expect_tx.shared.b64 _, [%0], %1;"
                         :: "r"(mb), "r"((uint32_t)CHUNK_BYTES) : "memory");
            asm volatile("cp.async.bulk.shared::cta.global.mbarrier::complete_tx::bytes "
                         "[%0], [%1], %2, [%3];"
                         :: "r"(sb), "l"(gin + cn * CHUNK_BYTES),
                            "r"((uint32_t)CHUNK_BYTES), "r"(mb) : "memory");
        }
    }

    double acc = (double)((s0 + s1) + (s2 + s3));

    // ---- block reduce (double, fixed tree) ----
    #pragma unroll
    for (int o = 16; o > 0; o >>= 1)
        acc += __shfl_xor_sync(0xffffffffu, acc, o);

    if (lane == 0) wd[wid] = acc;
    __syncthreads();

    if (wid == 0) {
        acc = (lane < NTHREADS / 32) ? wd[lane] : 0.0;
        #pragma unroll
        for (int o = 16; o > 0; o >>= 1)
            acc += __shfl_xor_sync(0xffffffffu, acc, o);
        if (lane == 0) g_partials[blockIdx.x] = acc;   // released by acq_rel
    }

    // ---- last-block election ----
    if (tid == 0) {
        unsigned int ticket;
        asm volatile("atom.add.acq_rel.gpu.u32 %0, [%1], 1;"
                     : "=r"(ticket) : "l"(&g_count) : "memory");
        s_is_last = (ticket == (unsigned int)(gridDim.x - 1));
    }
    __syncthreads();
    if (!s_is_last) return;

    // ---- final: reduce 592 doubles (deterministic fixed tree) ----
    double dsum = 0.0;
    for (int q = tid; q < NBLOCKS; q += NTHREADS)
        dsum += g_partials[q];

    #pragma unroll
    for (int o = 16; o > 0; o >>= 1)
        dsum += __shfl_xor_sync(0xffffffffu, dsum, o);

    if (lane == 0) wd[wid] = dsum;
    __syncthreads();

    if (wid == 0) {
        dsum = (lane < NTHREADS / 32) ? wd[lane] : 0.0;
        #pragma unroll
        for (int o = 16; o > 0; o >>= 1)
            dsum += __shfl_xor_sync(0xffffffffu, dsum, o);
        if (lane == 0) {
            out[0] = (float)(dsum * (double)scale);
            g_count = 0;  // reset for graph replay
        }
    }
}

extern "C" void kernel_launch(void* const* d_in, const int* in_sizes, int n_in,
                              void* d_out, int out_size)
{
    const float* x = (const float*)d_in[0];
    long long n = (long long)in_sizes[0];     // 134,217,728
    // 32768 chunks * 16KB = 512MiB exactly

    // B*C = n / (256*256) = 2048
    float scale = 1.0f / (float)(n / (256LL * 256LL));

    sqsum_tma_kernel<<<NBLOCKS, NTHREADS>>>((const char*)x,
                                            (float*)d_out, scale);
}